// round 16
// baseline (speedup 1.0000x reference)
#include <cuda_runtime.h>
#include <cuda_fp16.h>
#include <cstdint>

// ---------------- problem constants ----------------
#define B_SIZE 4096
#define C_CH   22
#define T_FULL 1002
#define T_IN   1001
#define K_OUT  40
#define KSZ    25
#define W_OUT  977
#define P_POOL 100
#define N_POOL 9
#define FEAT   360
#define O_OUT  4

// ---------------- tiling ----------------
#define NCP    11                 // channel pairs (22 channels exactly)
#define NROWX  12                 // 11 real rows + 1 zero row for pad slots
#define XROWH  536                // h2 per row (536 mod 32 = 24)
#define XPAIRS (XROWH/2)          // 268
#define SXH2   (NROWX*XROWH)      // 6432 half2 per buffer
#define NSLOT  275                // real (cp, t) K-pair slots
#define NSLOTP 280                // padded to 35 chunks of 8
#define NCHUNK 35
#define SWH2   (NSLOTP*K_OUT)     // 11200 half2
#define NTHR   512
#define NCTA   304                // 2 CTAs x 152 SMs, persistent
#define NITEM  (2*B_SIZE)         // (b, half) work items
#define ACCF   (FEAT + 2*K_OUT)   // spool + sb1 + sb2 per buffer (440 floats)

// smem byte offsets
#define SM_X     0                          // 2 x-buffers
#define SM_W     (2*SXH2*4)                 // 51456
#define SM_TBL   (SM_W + SWH2*4)            // 96256
#define SM_ACC   (SM_TBL + NSLOTP*4)        // 97376 : two ACCF buffers
#define SM_BIAS  (SM_ACC + 2*ACCF*4)        // 100896
#define SMEM_BYTES (SM_BIAS + K_OUT*4)      // 101056 -> 2 CTAs/SM

// ---------------- device scratch ----------------
__device__ uint32_t g_wh2[SWH2];
__device__ float g_pooled[(size_t)B_SIZE * FEAT];
__device__ float g_bnpart[(size_t)NITEM * 2 * K_OUT];
__device__ float g_scale[K_OUT];
__device__ float g_shift[K_OUT];

// ---------------- helpers ----------------
__device__ __forceinline__ void mma_f16(float* d,
                                        uint32_t a0, uint32_t a1, uint32_t a2, uint32_t a3,
                                        uint32_t b0, uint32_t b1) {
    asm volatile(
        "mma.sync.aligned.m16n8k16.row.col.f32.f16.f16.f32 "
        "{%0,%1,%2,%3}, {%4,%5,%6,%7}, {%8,%9}, {%0,%1,%2,%3};"
        : "+f"(d[0]), "+f"(d[1]), "+f"(d[2]), "+f"(d[3])
        : "r"(a0), "r"(a1), "r"(a2), "r"(a3), "r"(b0), "r"(b1));
}

// slot -> (cp, t):  t = slot / 11, cp = slot % 11   (slot < 275)
__global__ void prep_w_kernel(const float* __restrict__ cw) {
    int idx = blockIdx.x * blockDim.x + threadIdx.x;
    if (idx >= SWH2) return;
    int slot = idx / K_OUT;
    int k    = idx - slot * K_OUT;
    float v0 = 0.0f, v1 = 0.0f;
    if (slot < NSLOT) {
        int t  = slot / NCP;
        int cp = slot - t * NCP;
        v0 = cw[(k * C_CH + 2 * cp) * KSZ + t];
        v1 = cw[(k * C_CH + 2 * cp + 1) * KSZ + t];
    }
    half2 h = __floats2half2_rn(v0, v1);
    g_wh2[idx] = *(uint32_t*)&h;
}

// ---------------- staging: float2-vectorized, masked ----------------
__device__ __forceinline__ void stage_x(uint32_t* xb, const float* __restrict__ x,
                                        int bx, int tid) {
    const int b     = bx >> 1;
    const int wbase = (bx & 1) ? 500 : 0;
    const float* xg = x + (size_t)b * (C_CH * T_FULL);
#pragma unroll 1
    for (int i = tid; i < NROWX * XPAIRS; i += NTHR) {
        int cp = i / XPAIRS;
        int jp = i - cp * XPAIRS;
        int wl = 2 * jp;
        int wg = wbase + wl;
        uint2 out;
        if (cp < NCP && wg + 1 < T_IN) {
            // rows (2cp) and (2cp+1): both 8B-aligned at even wg (1002 stride)
            float2 r0 = *(const float2*)(xg + (2 * cp) * T_FULL + wg);
            float2 r1 = *(const float2*)(xg + (2 * cp + 1) * T_FULL + wg);
            half2 h0 = __floats2half2_rn(r0.x, r1.x);
            half2 h1 = __floats2half2_rn(r0.y, r1.y);
            out.x = *(uint32_t*)&h0;
            out.y = *(uint32_t*)&h1;
        } else if (cp < NCP && wg < T_IN) {
            float v0 = xg[(2 * cp) * T_FULL + wg];
            float v1 = xg[(2 * cp + 1) * T_FULL + wg];
            half2 h0 = __floats2half2_rn(v0, v1);
            out.x = *(uint32_t*)&h0;
            out.y = 0u;
        } else {
            out.x = 0u;
            out.y = 0u;
        }
        *(uint2*)(xb + cp * XROWH + wl) = out;
    }
}

// ---------------- drain + zero one acc buffer ----------------
__device__ __forceinline__ void drain_acc(float* ab, int pbx, int tid) {
    const int pb = pbx >> 1;
    const int ph = pbx & 1;
    float* spool = ab;
    float* sb1   = ab + FEAT;
    float* sb2   = sb1 + K_OUT;
    float* gp = g_pooled + (size_t)pb * FEAT;
#pragma unroll 1
    for (int i = tid; i < FEAT; i += NTHR) {
        int n = i - (i / N_POOL) * N_POOL;
        bool mine = ph ? (n >= 5) : (n < 5);
        if (mine) gp[i] = spool[i];
        spool[i] = 0.0f;                 // same thread read+zero: race-free
    }
    if (tid < K_OUT) {
        g_bnpart[(size_t)pbx * (2 * K_OUT) + tid]         = sb1[tid];
        g_bnpart[(size_t)pbx * (2 * K_OUT) + K_OUT + tid] = sb2[tid];
        sb1[tid] = 0.0f;
        sb2[tid] = 0.0f;
    }
}

// ---------------- pass 1: persistent, double-buffered, one sync/item ----------------
__global__ void __launch_bounds__(NTHR, 2)
conv_mma_kernel(const float* __restrict__ x, const float* __restrict__ bias) {
    extern __shared__ char smemc[];
    uint32_t* sxh2b = (uint32_t*)(smemc + SM_X);
    uint32_t* swh2  = (uint32_t*)(smemc + SM_W);
    int*      stbl  = (int*)(smemc + SM_TBL);
    float*    saccb = (float*)(smemc + SM_ACC);
    float*    sbias = (float*)(smemc + SM_BIAS);

    const int tid  = threadIdx.x;
    const int wid  = tid >> 5;
    const int lane = tid & 31;
    const int lg   = lane >> 2;
    const int lt   = lane & 3;

    // one-time staging: weights, slot table, bias, zero both acc buffers
    for (int i = tid; i < SWH2; i += NTHR) swh2[i] = g_wh2[i];
    for (int i = tid; i < NSLOTP; i += NTHR) {
        int off;
        if (i < NSLOT) {
            int t  = i / NCP;
            int cp = i - t * NCP;
            off = cp * XROWH + t;
        } else {
            off = NCP * XROWH;       // zero row
        }
        stbl[i] = off;
    }
    for (int i = tid; i < 2 * ACCF; i += NTHR) saccb[i] = 0.0f;
    if (tid < K_OUT) sbias[tid] = bias[tid];

    const int first = blockIdx.x;
    if (first < NITEM) stage_x(sxh2b, x, first, tid);
    __syncthreads();

    int par = 0;
    int lastbx = -1, lastp = 0;
    for (int bx = first; bx < NITEM; bx += NCTA) {
        const int half  = bx & 1;
        const int wbase = half ? 500 : 0;
        const int ntile = half ? 15 : 16;
        const int whi   = half ? W_OUT : 500;

        uint32_t* sxh2 = sxh2b + par * SXH2;
        float* spool = saccb + par * ACCF;
        float* sb1   = spool + FEAT;
        float* sb2   = sb1 + K_OUT;

        float acc[2][5][4];
        const bool active = (wid < ntile);
        if (active) {
#pragma unroll
            for (int ti = 0; ti < 2; ti++)
#pragma unroll
                for (int nt = 0; nt < 5; nt++)
#pragma unroll
                    for (int r = 0; r < 4; r++) acc[ti][nt][r] = 0.0f;

            const int owl = 32 * wid + lg;
            for (int ch = 0; ch < NCHUNK; ch++) {
                const uint32_t* wb = swh2 + ch * 8 * K_OUT;
                uint32_t bb[5][2];
#pragma unroll
                for (int nt = 0; nt < 5; nt++) {
                    int col = 8 * nt + lg;
                    bb[nt][0] = wb[lt * K_OUT + col];
                    bb[nt][1] = wb[(lt + 4) * K_OUT + col];
                }
                const int tb0 = stbl[ch * 8 + lt];
                const int tb2 = stbl[ch * 8 + lt + 4];
#pragma unroll
                for (int ti = 0; ti < 2; ti++) {
                    int o = owl + 16 * ti;
                    uint32_t a0 = sxh2[tb0 + o];
                    uint32_t a1 = sxh2[tb0 + o + 8];
                    uint32_t a2 = sxh2[tb2 + o];
                    uint32_t a3 = sxh2[tb2 + o + 8];
#pragma unroll
                    for (int nt = 0; nt < 5; nt++)
                        mma_f16(acc[ti][nt], a0, a1, a2, a3, bb[nt][0], bb[nt][1]);
                }
            }
        }

        // drain previous item (other acc buffer) — light, runs under live acc
        if (bx != first) drain_acc(saccb + (par ^ 1) * ACCF, bx - NCTA, tid);

        // epilogue: bias + ELU + BN stats + pooling (consumes acc)
        if (active) {
            const int w0 = wbase + wid * 32;
            const int p0 = w0 / P_POOL;
#pragma unroll
            for (int nt = 0; nt < 5; nt++) {
#pragma unroll
                for (int rk = 0; rk < 2; rk++) {
                    const int k = 8 * nt + 2 * lt + rk;
                    const float bk = sbias[k];
                    float s1 = 0.f, s2 = 0.f, q0 = 0.f, q1 = 0.f;
#pragma unroll
                    for (int ti = 0; ti < 2; ti++) {
#pragma unroll
                        for (int rh = 0; rh < 2; rh++) {
                            int w = w0 + 16 * ti + lg + 8 * rh;
                            float v = acc[ti][nt][2 * rh + rk] + bk;
                            float y = v > 0.0f ? v : (__expf(v) - 1.0f);
                            if (w < whi) {
                                s1 += y;
                                s2 += y * y;
                                if (w < N_POOL * P_POOL) {
                                    float pv = y * 0.01f;
                                    if (w / P_POOL == p0) q0 += pv; else q1 += pv;
                                }
                            }
                        }
                    }
#pragma unroll
                    for (int off = 4; off < 32; off <<= 1) {
                        s1 += __shfl_xor_sync(0xffffffffu, s1, off);
                        s2 += __shfl_xor_sync(0xffffffffu, s2, off);
                        q0 += __shfl_xor_sync(0xffffffffu, q0, off);
                        q1 += __shfl_xor_sync(0xffffffffu, q1, off);
                    }
                    if (lg == 0) {
                        atomicAdd(&sb1[k], s1);
                        atomicAdd(&sb2[k], s2);
                        if (p0 < N_POOL)     atomicAdd(&spool[k * N_POOL + p0], q0);
                        if (p0 + 1 < N_POOL) atomicAdd(&spool[k * N_POOL + p0 + 1], q1);
                    }
                }
            }
        }

        // stage next item into the other x buffer (acc is dead here)
        if (bx + NCTA < NITEM) stage_x(sxh2b + (par ^ 1) * SXH2, x, bx + NCTA, tid);

        __syncthreads();   // staging STS, epilogue atomics, drain zeroing all visible
        lastbx = bx;
        lastp  = par;
        par ^= 1;
    }

    // drain the final item (sync above guarantees its atomics are done)
    if (lastbx >= 0) drain_acc(saccb + lastp * ACCF, lastbx, tid);
}

// ---------------- pass 2: BN stats reduce ----------------
__global__ void bn_reduce_kernel(const float* __restrict__ gamma,
                                 const float* __restrict__ beta) {
    __shared__ float r1[256];
    __shared__ float r2[256];
    int k = blockIdx.x;
    int tid = threadIdx.x;
    float s1 = 0.0f, s2 = 0.0f;
    for (int bx = tid; bx < NITEM; bx += 256) {
        s1 += g_bnpart[(size_t)bx * (2 * K_OUT) + k];
        s2 += g_bnpart[(size_t)bx * (2 * K_OUT) + K_OUT + k];
    }
    r1[tid] = s1; r2[tid] = s2;
    __syncthreads();
    for (int s = 128; s > 0; s >>= 1) {
        if (tid < s) { r1[tid] += r1[tid + s]; r2[tid] += r2[tid + s]; }
        __syncthreads();
    }
    if (tid == 0) {
        const float N = (float)((size_t)B_SIZE * W_OUT);
        float mean = r1[0] / N;
        float var  = r2[0] / N - mean * mean;
        float sc   = gamma[k] * rsqrtf(var + 1e-5f);
        g_scale[k] = sc;
        g_shift[k] = beta[k] - mean * sc;
    }
}

// ---------------- pass 3: subject-gathered FC (warp per sample) ----------------
__global__ void fc_kernel(const float* __restrict__ x,
                          const float* __restrict__ fc_w,
                          const float* __restrict__ fc_b,
                          float* __restrict__ out) {
    int wid  = threadIdx.x >> 5;
    int lane = threadIdx.x & 31;
    int b = blockIdx.x * 8 + wid;
    if (b >= B_SIZE) return;
    int sid = __float2int_rn(x[(size_t)b * (C_CH * T_FULL) + T_IN] * 1e-6f) - 1;
    const float4* Wp = (const float4*)(fc_w + (size_t)sid * FEAT * O_OUT);
    const float*  pf = g_pooled + (size_t)b * FEAT;
    float a0 = 0.f, a1 = 0.f, a2 = 0.f, a3 = 0.f;
#pragma unroll
    for (int j = 0; j < 12; j++) {
        int f = lane + j * 32;
        if (f < FEAT) {
            int k = f / N_POOL;
            float v = pf[f] * g_scale[k] + g_shift[k];
            float4 wv = Wp[f];
            a0 += v * wv.x; a1 += v * wv.y; a2 += v * wv.z; a3 += v * wv.w;
        }
    }
#pragma unroll
    for (int off = 16; off > 0; off >>= 1) {
        a0 += __shfl_xor_sync(0xffffffffu, a0, off);
        a1 += __shfl_xor_sync(0xffffffffu, a1, off);
        a2 += __shfl_xor_sync(0xffffffffu, a2, off);
        a3 += __shfl_xor_sync(0xffffffffu, a3, off);
    }
    if (lane == 0) {
        const float* fb = fc_b + sid * O_OUT;
        float4 o = make_float4(a0 + fb[0], a1 + fb[1], a2 + fb[2], a3 + fb[3]);
        ((float4*)out)[b] = o;
    }
}

// ---------------- launch ----------------
extern "C" void kernel_launch(void* const* d_in, const int* in_sizes, int n_in,
                              void* d_out, int out_size) {
    const float* x      = (const float*)d_in[0];
    const float* conv_w = (const float*)d_in[1];
    const float* conv_b = (const float*)d_in[2];
    const float* gamma  = (const float*)d_in[3];
    const float* beta   = (const float*)d_in[4];
    const float* fc_w   = (const float*)d_in[5];
    const float* fc_b   = (const float*)d_in[6];
    float* out = (float*)d_out;

    cudaFuncSetAttribute(conv_mma_kernel,
                         cudaFuncAttributeMaxDynamicSharedMemorySize, SMEM_BYTES);

    prep_w_kernel<<<(SWH2 + 255) / 256, 256>>>(conv_w);
    conv_mma_kernel<<<NCTA, NTHR, SMEM_BYTES>>>(x, conv_b);
    bn_reduce_kernel<<<K_OUT, 256>>>(gamma, beta);
    fc_kernel<<<B_SIZE / 8, 256>>>(x, fc_w, fc_b, out);
}

// round 17
// speedup vs baseline: 1.2277x; 1.2277x over previous
#include <cuda_runtime.h>
#include <cuda_fp16.h>
#include <cstdint>

// ---------------- problem constants ----------------
#define B_SIZE 4096
#define C_CH   22
#define T_FULL 1002
#define T_IN   1001
#define K_OUT  40
#define KSZ    25
#define W_OUT  977
#define P_POOL 100
#define N_POOL 9
#define FEAT   360
#define O_OUT  4

// ---------------- tiling ----------------
#define NCP    11                 // channel pairs (22 channels exactly)
#define NROWX  12                 // 11 real rows + 1 zero row for pad slots
#define XROWH  536                // h2 per row (536 mod 32 = 24)
#define XPAIRS (XROWH/2)          // 268
#define SXH2   (NROWX*XROWH)      // 6432 half2
#define NSLOT  275                // real (cp, t) K-pair slots
#define NSLOTP 280                // padded to 35 chunks of 8
#define NCHUNK 35
#define SWH2   (NSLOTP*K_OUT)     // 11200 half2
#define NTHR   512
#define NCTA   304                // 2 CTAs x 152 SMs, persistent
#define NITEM  (2*B_SIZE)         // (b, half) work items

// smem byte offsets
#define SM_X     0
#define SM_W     (SXH2*4)                  // 25728
#define SM_TBL   (SM_W + SWH2*4)           // 70528
#define SM_POOL  (SM_TBL + NSLOTP*4)       // 71648
#define SM_B1    (SM_POOL + FEAT*4)        // 73088
#define SM_B2    (SM_B1 + K_OUT*4)         // 73248
#define SM_BIAS  (SM_B2 + K_OUT*4)         // 73408
#define SMEM_BYTES (SM_BIAS + K_OUT*4)     // 73568 -> 2 CTAs/SM

// ---------------- device scratch ----------------
__device__ uint32_t g_wh2[SWH2];                       // [slot280][k40] half2
__device__ float g_pooled[(size_t)B_SIZE * FEAT];
__device__ float g_bnpart[(size_t)NITEM * 2 * K_OUT];
__device__ float g_scale[K_OUT];
__device__ float g_shift[K_OUT];

// ---------------- helpers ----------------
__device__ __forceinline__ void mma_f16(float* d,
                                        uint32_t a0, uint32_t a1, uint32_t a2, uint32_t a3,
                                        uint32_t b0, uint32_t b1) {
    asm volatile(
        "mma.sync.aligned.m16n8k16.row.col.f32.f16.f16.f32 "
        "{%0,%1,%2,%3}, {%4,%5,%6,%7}, {%8,%9}, {%0,%1,%2,%3};"
        : "+f"(d[0]), "+f"(d[1]), "+f"(d[2]), "+f"(d[3])
        : "r"(a0), "r"(a1), "r"(a2), "r"(a3), "r"(b0), "r"(b1));
}

// slot -> (cp, t):  t = slot / 11, cp = slot % 11   (slot < 275)
// ---------------- pass 0: weights -> [slot][k40] channel-pair half2 ----------------
__global__ void prep_w_kernel(const float* __restrict__ cw) {
    int idx = blockIdx.x * blockDim.x + threadIdx.x;
    if (idx >= SWH2) return;
    int slot = idx / K_OUT;
    int k    = idx - slot * K_OUT;
    float v0 = 0.0f, v1 = 0.0f;
    if (slot < NSLOT) {
        int t  = slot / NCP;
        int cp = slot - t * NCP;
        v0 = cw[(k * C_CH + 2 * cp) * KSZ + t];
        v1 = cw[(k * C_CH + 2 * cp + 1) * KSZ + t];
    }
    half2 h = __floats2half2_rn(v0, v1);
    g_wh2[idx] = *(uint32_t*)&h;
}

// ---------------- pass 1: persistent f16 mma conv + ELU + pool + BN partials ----------------
// items bx = b*2 + half.  half0: w in [0,500) bins 0-4 (16 tiles),
//                         half1: w in [500,977) bins 5-8 (15 tiles)
__global__ void __launch_bounds__(NTHR, 2)
conv_mma_kernel(const float* __restrict__ x, const float* __restrict__ bias) {
    extern __shared__ char smemc[];
    uint32_t* sxh2  = (uint32_t*)(smemc + SM_X);
    uint32_t* swh2  = (uint32_t*)(smemc + SM_W);
    int*      stbl  = (int*)(smemc + SM_TBL);
    float*    spool = (float*)(smemc + SM_POOL);
    float*    sb1   = (float*)(smemc + SM_B1);
    float*    sb2   = (float*)(smemc + SM_B2);
    float*    sbias = (float*)(smemc + SM_BIAS);

    const int tid  = threadIdx.x;
    const int wid  = tid >> 5;        // 0..15
    const int lane = tid & 31;
    const int lg   = lane >> 2;       // group id (w row)
    const int lt   = lane & 3;        // thread-in-group

    // stage weights + slot table + bias ONCE per persistent CTA
    for (int i = tid; i < SWH2; i += NTHR) swh2[i] = g_wh2[i];
    for (int i = tid; i < NSLOTP; i += NTHR) {
        int off;
        if (i < NSLOT) {
            int t  = i / NCP;
            int cp = i - t * NCP;
            off = cp * XROWH + t;
        } else {
            off = NCP * XROWH;       // zero row
        }
        stbl[i] = off;
    }
    if (tid < K_OUT) sbias[tid] = bias[tid];

    for (int bx = blockIdx.x; bx < NITEM; bx += NCTA) {
        const int b    = bx >> 1;
        const int half = bx & 1;
        const int wbase = half ? 500 : 0;
        const int ntile = half ? 15 : 16;
        const int whi   = half ? W_OUT : 500;

        __syncthreads();   // prev item's smem reads complete

        // stage x window (float2-vectorized): row cp holds half2 (x[2cp][w], x[2cp+1][w])
        const float* xg = x + (size_t)b * (C_CH * T_FULL);
#pragma unroll 1
        for (int i = tid; i < NROWX * XPAIRS; i += NTHR) {
            int cp = i / XPAIRS;
            int jp = i - cp * XPAIRS;
            int wl = 2 * jp;
            int wg = wbase + wl;
            uint2 out2;
            if (cp < NCP && wg + 1 < T_IN) {
                // rows (2cp), (2cp+1): 8B-aligned at even wg (stride 1002)
                float2 r0 = *(const float2*)(xg + (2 * cp) * T_FULL + wg);
                float2 r1 = *(const float2*)(xg + (2 * cp + 1) * T_FULL + wg);
                half2 h0 = __floats2half2_rn(r0.x, r1.x);
                half2 h1 = __floats2half2_rn(r0.y, r1.y);
                out2.x = *(uint32_t*)&h0;
                out2.y = *(uint32_t*)&h1;
            } else if (cp < NCP && wg < T_IN) {
                float v0 = xg[(2 * cp) * T_FULL + wg];
                float v1 = xg[(2 * cp + 1) * T_FULL + wg];
                half2 h0 = __floats2half2_rn(v0, v1);
                out2.x = *(uint32_t*)&h0;
                out2.y = 0u;
            } else {
                out2.x = 0u;
                out2.y = 0u;
            }
            *(uint2*)(sxh2 + cp * XROWH + wl) = out2;
        }
        for (int i = tid; i < FEAT + 2 * K_OUT; i += NTHR) spool[i] = 0.0f;
        __syncthreads();

        if (wid < ntile) {
            const int w0  = wbase + wid * 32;   // global tile start
            const int owl = 32 * wid + lg;      // local w for ti=0 (ti=1: +16)

            float acc[2][5][4];
#pragma unroll
            for (int ti = 0; ti < 2; ti++)
#pragma unroll
                for (int nt = 0; nt < 5; nt++)
#pragma unroll
                    for (int r = 0; r < 4; r++) acc[ti][nt][r] = 0.0f;

            for (int ch = 0; ch < NCHUNK; ch++) {
                const uint32_t* wb = swh2 + ch * 8 * K_OUT;
                uint32_t bb[5][2];
#pragma unroll
                for (int nt = 0; nt < 5; nt++) {
                    int col = 8 * nt + lg;
                    bb[nt][0] = wb[lt * K_OUT + col];
                    bb[nt][1] = wb[(lt + 4) * K_OUT + col];
                }
                const int tb0 = stbl[ch * 8 + lt];
                const int tb2 = stbl[ch * 8 + lt + 4];
#pragma unroll
                for (int ti = 0; ti < 2; ti++) {
                    int o = owl + 16 * ti;
                    uint32_t a0 = sxh2[tb0 + o];
                    uint32_t a1 = sxh2[tb0 + o + 8];
                    uint32_t a2 = sxh2[tb2 + o];
                    uint32_t a3 = sxh2[tb2 + o + 8];
#pragma unroll
                    for (int nt = 0; nt < 5; nt++)
                        mma_f16(acc[ti][nt], a0, a1, a2, a3, bb[nt][0], bb[nt][1]);
                }
            }

            // epilogue: bias + ELU + BN stats + pooling, fragment-resident
            const int p0 = w0 / P_POOL;
#pragma unroll
            for (int nt = 0; nt < 5; nt++) {
#pragma unroll
                for (int rk = 0; rk < 2; rk++) {
                    const int k = 8 * nt + 2 * lt + rk;
                    const float bk = sbias[k];
                    float s1 = 0.f, s2 = 0.f, q0 = 0.f, q1 = 0.f;
#pragma unroll
                    for (int ti = 0; ti < 2; ti++) {
#pragma unroll
                        for (int rh = 0; rh < 2; rh++) {
                            int w = w0 + 16 * ti + lg + 8 * rh;
                            float v = acc[ti][nt][2 * rh + rk] + bk;
                            float y = v > 0.0f ? v : (__expf(v) - 1.0f);
                            if (w < whi) {
                                s1 += y;
                                s2 += y * y;
                                if (w < N_POOL * P_POOL) {
                                    float pv = y * 0.01f;
                                    if (w / P_POOL == p0) q0 += pv; else q1 += pv;
                                }
                            }
                        }
                    }
#pragma unroll
                    for (int off = 4; off < 32; off <<= 1) {
                        s1 += __shfl_xor_sync(0xffffffffu, s1, off);
                        s2 += __shfl_xor_sync(0xffffffffu, s2, off);
                        q0 += __shfl_xor_sync(0xffffffffu, q0, off);
                        q1 += __shfl_xor_sync(0xffffffffu, q1, off);
                    }
                    if (lg == 0) {
                        atomicAdd(&sb1[k], s1);
                        atomicAdd(&sb2[k], s2);
                        if (p0 < N_POOL)     atomicAdd(&spool[k * N_POOL + p0], q0);
                        if (p0 + 1 < N_POOL) atomicAdd(&spool[k * N_POOL + p0 + 1], q1);
                    }
                }
            }
        }
        __syncthreads();

        // write only this half's pool bins (disjoint across the two halves of b)
        float* gp = g_pooled + (size_t)b * FEAT;
        for (int i = tid; i < FEAT; i += NTHR) {
            int n = i - (i / N_POOL) * N_POOL;
            bool mine = half ? (n >= 5) : (n < 5);
            if (mine) gp[i] = spool[i];
        }
        if (tid < K_OUT) {
            g_bnpart[(size_t)bx * (2 * K_OUT) + tid]         = sb1[tid];
            g_bnpart[(size_t)bx * (2 * K_OUT) + K_OUT + tid] = sb2[tid];
        }
    }
}

// ---------------- pass 2: BN stats reduce (over 2B partials) ----------------
__global__ void bn_reduce_kernel(const float* __restrict__ gamma,
                                 const float* __restrict__ beta) {
    __shared__ float r1[256];
    __shared__ float r2[256];
    int k = blockIdx.x;
    int tid = threadIdx.x;
    float s1 = 0.0f, s2 = 0.0f;
    for (int bx = tid; bx < NITEM; bx += 256) {
        s1 += g_bnpart[(size_t)bx * (2 * K_OUT) + k];
        s2 += g_bnpart[(size_t)bx * (2 * K_OUT) + K_OUT + k];
    }
    r1[tid] = s1; r2[tid] = s2;
    __syncthreads();
    for (int s = 128; s > 0; s >>= 1) {
        if (tid < s) { r1[tid] += r1[tid + s]; r2[tid] += r2[tid + s]; }
        __syncthreads();
    }
    if (tid == 0) {
        const float N = (float)((size_t)B_SIZE * W_OUT);
        float mean = r1[0] / N;
        float var  = r2[0] / N - mean * mean;
        float sc   = gamma[k] * rsqrtf(var + 1e-5f);
        g_scale[k] = sc;
        g_shift[k] = beta[k] - mean * sc;
    }
}

// ---------------- pass 3: subject-gathered FC (warp per sample) ----------------
__global__ void fc_kernel(const float* __restrict__ x,
                          const float* __restrict__ fc_w,
                          const float* __restrict__ fc_b,
                          float* __restrict__ out) {
    int wid  = threadIdx.x >> 5;
    int lane = threadIdx.x & 31;
    int b = blockIdx.x * 8 + wid;
    if (b >= B_SIZE) return;
    int sid = __float2int_rn(x[(size_t)b * (C_CH * T_FULL) + T_IN] * 1e-6f) - 1;
    const float4* Wp = (const float4*)(fc_w + (size_t)sid * FEAT * O_OUT);
    const float*  pf = g_pooled + (size_t)b * FEAT;
    float a0 = 0.f, a1 = 0.f, a2 = 0.f, a3 = 0.f;
#pragma unroll
    for (int j = 0; j < 12; j++) {
        int f = lane + j * 32;
        if (f < FEAT) {
            int k = f / N_POOL;
            float v = pf[f] * g_scale[k] + g_shift[k];
            float4 wv = Wp[f];
            a0 += v * wv.x; a1 += v * wv.y; a2 += v * wv.z; a3 += v * wv.w;
        }
    }
#pragma unroll
    for (int off = 16; off > 0; off >>= 1) {
        a0 += __shfl_xor_sync(0xffffffffu, a0, off);
        a1 += __shfl_xor_sync(0xffffffffu, a1, off);
        a2 += __shfl_xor_sync(0xffffffffu, a2, off);
        a3 += __shfl_xor_sync(0xffffffffu, a3, off);
    }
    if (lane == 0) {
        const float* fb = fc_b + sid * O_OUT;
        float4 o = make_float4(a0 + fb[0], a1 + fb[1], a2 + fb[2], a3 + fb[3]);
        ((float4*)out)[b] = o;
    }
}

// ---------------- launch ----------------
extern "C" void kernel_launch(void* const* d_in, const int* in_sizes, int n_in,
                              void* d_out, int out_size) {
    const float* x      = (const float*)d_in[0];
    const float* conv_w = (const float*)d_in[1];
    const float* conv_b = (const float*)d_in[2];
    const float* gamma  = (const float*)d_in[3];
    const float* beta   = (const float*)d_in[4];
    const float* fc_w   = (const float*)d_in[5];
    const float* fc_b   = (const float*)d_in[6];
    float* out = (float*)d_out;

    cudaFuncSetAttribute(conv_mma_kernel,
                         cudaFuncAttributeMaxDynamicSharedMemorySize, SMEM_BYTES);

    prep_w_kernel<<<(SWH2 + 255) / 256, 256>>>(conv_w);
    conv_mma_kernel<<<NCTA, NTHR, SMEM_BYTES>>>(x, conv_b);
    bn_reduce_kernel<<<K_OUT, 256>>>(gamma, beta);
    fc_kernel<<<B_SIZE / 8, 256>>>(x, fc_w, fc_b, out);
}